// round 9
// baseline (speedup 1.0000x reference)
#include <cuda_runtime.h>
#include <cuda_fp16.h>

// warp3D: out[b,c,z,y,x] = trilinear gather of I at (x+fx, y+fy, z+fz)
// B=2, C=2, D=160, H=192, W=224, fp32 in/out.
//
// Pass 1: pack I -> fp16 QUAD per voxel (16 B):
//   Q[b,z,y,x] = { h2(c0,c1)@(y,x), h2@(y,x+1), h2@(y+1,x), h2@(y+1,x+1) }
//   (x=W-1 / y=H-1 edge-duplicated).
// Pass 2: per voxel, the 8 trilinear corners come from TWO LDG.128
//   (one quad at (z0,y0,x0), one at (z1,y0,x0)); x/y clamp cases are
//   in-register selects. 2 voxels per thread (y-pair) for MLP.

#define Wd 224
#define Hd 192
#define Dd 160
#define Bd 2
#define HWd (Hd * Wd)            // 43008
#define DHWd (Dd * HWd)          // 6881280

__device__ __forceinline__ unsigned int h2_to_u(__half2 h) {
    return *reinterpret_cast<unsigned int*>(&h);
}
__device__ __forceinline__ __half2 u_to_h2(unsigned int u) {
    return *reinterpret_cast<__half2*>(&u);
}

// 13.76M voxels * 16B = 220 MB scratch
__device__ uint4 g_Q[(long)Bd * DHWd];

// Pack: thread = x-pair at one y; reads rows y and y+1; 2 x STG.128.
__global__ __launch_bounds__(224) void pack_kernel(const float* __restrict__ I)
{
    const int m = threadIdx.x;                 // 0..111 (x pair = 2m, 2m+1)
    const int y = blockIdx.x * 2 + threadIdx.y;
    const int z = blockIdx.y;
    const int b = blockIdx.z;

    const int x = 2 * m;
    const int s = z * HWd + y * Wd + x;
    const float* __restrict__ I0 = I + (long)b * 2 * DHWd;
    const float* __restrict__ I1 = I0 + DHWd;

    const int yn = min(y + 1, Hd - 1);
    const int sy = z * HWd + yn * Wd + x;
    const int xe = min(x + 2, Wd - 1) - x;     // offset of x+2 (edge-clamped)

    // row y
    const float2 a0 = __ldg((const float2*)(I0 + s));
    const float2 a1 = __ldg((const float2*)(I1 + s));
    const float  na0 = __ldg(I0 + s + xe);
    const float  na1 = __ldg(I1 + s + xe);
    // row y+1
    const float2 b0 = __ldg((const float2*)(I0 + sy));
    const float2 b1 = __ldg((const float2*)(I1 + sy));
    const float  nb0 = __ldg(I0 + sy + xe);
    const float  nb1 = __ldg(I1 + sy + xe);

    const unsigned int ax  = h2_to_u(__floats2half2_rn(a0.x, a1.x));  // (y,   x)
    const unsigned int ax1 = h2_to_u(__floats2half2_rn(a0.y, a1.y));  // (y,   x+1)
    const unsigned int ax2 = h2_to_u(__floats2half2_rn(na0,  na1));   // (y,   x+2)
    const unsigned int bx  = h2_to_u(__floats2half2_rn(b0.x, b1.x));  // (y+1, x)
    const unsigned int bx1 = h2_to_u(__floats2half2_rn(b0.y, b1.y));  // (y+1, x+1)
    const unsigned int bx2 = h2_to_u(__floats2half2_rn(nb0,  nb1));   // (y+1, x+2)

    uint4* __restrict__ Qb = g_Q + (long)b * DHWd;
    Qb[s]     = make_uint4(ax,  ax1, bx,  bx1);   // voxel x
    Qb[s + 1] = make_uint4(ax1, ax2, bx1, bx2);   // voxel x+1
}

// Gather: block 224 = one x-row; each thread does 2 voxels (y, y+1).
__global__ __launch_bounds__(Wd) void warp3d_kernel(
    const float* __restrict__ flow,
    float* __restrict__ out)
{
    const int x  = threadIdx.x;        // 0..223
    const int yb = blockIdx.x * 2;
    const int z  = blockIdx.y;
    const int b  = blockIdx.z;

    const float* __restrict__ fb = flow + (long)b * 3 * DHWd;
    const uint4* __restrict__ Qb = g_Q + (long)b * DHWd;
    float* __restrict__ ob = out + (long)b * 2 * DHWd;

    int   sv[2];
    float w00[2], w10[2], w01[2], w11[2], dzv[2], ezv[2];
    uint4 Q0[2], Q1[2];
    bool  xeq[2], yeq[2];

    // Phase 1: coords + all loads in flight (6 flow + 4 quad LDG.128)
#pragma unroll
    for (int v = 0; v < 2; ++v) {
        const int y = yb + v;
        const int s = z * HWd + y * Wd + x;
        sv[v] = s;

        const float fx = __ldg(fb + s);
        const float fy = __ldg(fb + s + DHWd);
        const float fz = __ldg(fb + s + 2L * DHWd);

        const float xf = fx + (float)x;
        const float yf = fy + (float)y;
        const float zf = fz + (float)z;

        int x0 = (int)floorf(xf);
        int y0 = (int)floorf(yf);
        int z0 = (int)floorf(zf);
        // upper corner from UNclamped lower+1, then clamp (matches ref)
        const int x1 = min(max(x0 + 1, 0), Wd - 1);
        const int y1 = min(max(y0 + 1, 0), Hd - 1);
        const int z1 = min(max(z0 + 1, 0), Dd - 1);
        x0 = min(max(x0, 0), Wd - 1);
        y0 = min(max(y0, 0), Hd - 1);
        z0 = min(max(z0, 0), Dd - 1);

        const float dx = (float)x1 - xf;
        const float dy = (float)y1 - yf;
        const float dz = (float)z1 - zf;
        const float ex = 1.0f - dx;
        const float ey = 1.0f - dy;

        w00[v] = dx * dy;    // (y0, x0)
        w01[v] = ex * dy;    // (y0, x1)
        w10[v] = dx * ey;    // (y1, x0)
        w11[v] = ex * ey;    // (y1, x1)
        dzv[v] = dz;
        ezv[v] = 1.0f - dz;
        xeq[v] = (x1 == x0);
        yeq[v] = (y1 == y0);

        const int r0 = z0 * HWd + y0 * Wd + x0;
        const int r1 = z1 * HWd + y0 * Wd + x0;
        Q0[v] = __ldg(Qb + r0);
        Q1[v] = __ldg(Qb + r1);
    }

    // Phase 2: clamp-fix, convert, reduce, store
#pragma unroll
    for (int v = 0; v < 2; ++v) {
        if (xeq[v]) {           // x1==x0: x+1 slots := x slots
            Q0[v].y = Q0[v].x;  Q0[v].w = Q0[v].z;
            Q1[v].y = Q1[v].x;  Q1[v].w = Q1[v].z;
        }
        if (yeq[v]) {           // y1==y0: y+1 slots := y slots
            Q0[v].z = Q0[v].x;  Q0[v].w = Q0[v].y;
            Q1[v].z = Q1[v].x;  Q1[v].w = Q1[v].y;
        }

        const float2 a00 = __half22float2(u_to_h2(Q0[v].x));  // z0 (y0,x0)
        const float2 a01 = __half22float2(u_to_h2(Q0[v].y));  // z0 (y0,x1)
        const float2 a10 = __half22float2(u_to_h2(Q0[v].z));  // z0 (y1,x0)
        const float2 a11 = __half22float2(u_to_h2(Q0[v].w));  // z0 (y1,x1)
        const float2 c00 = __half22float2(u_to_h2(Q1[v].x));  // z1 (y0,x0)
        const float2 c01 = __half22float2(u_to_h2(Q1[v].y));
        const float2 c10 = __half22float2(u_to_h2(Q1[v].z));
        const float2 c11 = __half22float2(u_to_h2(Q1[v].w));

        const float p0c0 = w00[v]*a00.x + w01[v]*a01.x + w10[v]*a10.x + w11[v]*a11.x;
        const float p0c1 = w00[v]*a00.y + w01[v]*a01.y + w10[v]*a10.y + w11[v]*a11.y;
        const float p1c0 = w00[v]*c00.x + w01[v]*c01.x + w10[v]*c10.x + w11[v]*c11.x;
        const float p1c1 = w00[v]*c00.y + w01[v]*c01.y + w10[v]*c10.y + w11[v]*c11.y;

        ob[sv[v]]        = dzv[v] * p0c0 + ezv[v] * p1c0;
        ob[sv[v] + DHWd] = dzv[v] * p0c1 + ezv[v] * p1c1;
    }
}

extern "C" void kernel_launch(void* const* d_in, const int* in_sizes, int n_in,
                              void* d_out, int out_size)
{
    const float* I    = (const float*)d_in[0];
    const float* flow = (const float*)d_in[1];
    float* out        = (float*)d_out;

    dim3 pblock(112, 2, 1);                 // 224 thr
    dim3 pgrid(Hd / 2, Dd, Bd);
    pack_kernel<<<pgrid, pblock>>>(I);

    dim3 block(Wd, 1, 1);                   // 224 thr
    dim3 grid(Hd / 2, Dd, Bd);              // 96 x 160 x 2
    warp3d_kernel<<<grid, block>>>(flow, out);
}

// round 10
// speedup vs baseline: 1.2563x; 1.2563x over previous
#include <cuda_runtime.h>
#include <cuda_fp16.h>

// warp3D: out[b,c,z,y,x] = trilinear gather of I at (x+fx, y+fy, z+fz)
// B=2, C=2, D=160, H=192, W=224, fp32 in/out.
//
// Pass 1 (R7 layout): pack I -> fp16 "half4" per voxel (8 B):
//   It[b,z,y,x] = h(c0[x]), h(c1[x]), h(c0[x+1]), h(c1[x+1])
// Pass 2: 4 x 8B gathers per voxel; FOUR voxels per thread (y-quad),
//   all loads issued before any reduction for max MLP.

#define Wd 224
#define Hd 192
#define Dd 160
#define Bd 2
#define HWd (Hd * Wd)            // 43008
#define DHWd (Dd * HWd)          // 6881280
#define VPT 4                    // voxels per thread (along y)

__device__ __forceinline__ unsigned int h2_to_u(__half2 h) {
    return *reinterpret_cast<unsigned int*>(&h);
}
__device__ __forceinline__ __half2 u_to_h2(unsigned int u) {
    return *reinterpret_cast<__half2*>(&u);
}

// 13.76M voxels * 8B = 110 MB scratch
__device__ uint2 g_It[(long)Bd * DHWd];

// Pack: 2 voxels/thread, float2 loads, one STG.128 per pair.
__global__ __launch_bounds__(224) void pack_kernel(const float* __restrict__ I)
{
    const int m = threadIdx.x;                 // 0..111 (x pair = 2m, 2m+1)
    const int y = blockIdx.x * 2 + threadIdx.y;
    const int z = blockIdx.y;
    const int b = blockIdx.z;

    const int x = 2 * m;
    const int s = z * HWd + y * Wd + x;
    const float* __restrict__ I0 = I + (long)b * 2 * DHWd;
    const float* __restrict__ I1 = I0 + DHWd;

    const float2 a = __ldg((const float2*)(I0 + s));   // c0[x], c0[x+1]
    const float2 c = __ldg((const float2*)(I1 + s));   // c1[x], c1[x+1]
    const int sn = s - x + min(x + 2, Wd - 1);          // x+2, edge-clamped
    const float n0 = __ldg(I0 + sn);
    const float n1 = __ldg(I1 + sn);

    const unsigned int lo0 = h2_to_u(__floats2half2_rn(a.x, c.x));
    const unsigned int mid = h2_to_u(__floats2half2_rn(a.y, c.y));
    const unsigned int hi1 = h2_to_u(__floats2half2_rn(n0, n1));

    uint4 v;
    v.x = lo0; v.y = mid;      // voxel x
    v.z = mid; v.w = hi1;      // voxel x+1
    *reinterpret_cast<uint4*>(g_It + (long)b * DHWd + s) = v;
}

// Gather: block 224 thr = one x-row; each thread does VPT voxels (y..y+3).
__global__ __launch_bounds__(Wd) void warp3d_kernel(
    const float* __restrict__ flow,
    float* __restrict__ out)
{
    const int x  = threadIdx.x;          // 0..223
    const int yb = blockIdx.x * VPT;     // 0..188 step 4
    const int z  = blockIdx.y;           // 0..159
    const int b  = blockIdx.z;           // 0..1

    const float* __restrict__ fb = flow + (long)b * 3 * DHWd;
    const uint2* __restrict__ Ic = g_It + (long)b * DHWd;
    float* __restrict__ ob = out + (long)b * 2 * DHWd;

    const int s0 = z * HWd + yb * Wd + x;

    // ---- Stage A: all flow loads in flight (12 LDG.32) ----
    float fxv[VPT], fyv[VPT], fzv[VPT];
#pragma unroll
    for (int v = 0; v < VPT; ++v) {
        const int s = s0 + v * Wd;
        fxv[v] = __ldg(fb + s);
        fyv[v] = __ldg(fb + s + DHWd);
        fzv[v] = __ldg(fb + s + 2L * DHWd);
    }

    // ---- Stage B: coords + all gathers in flight (16 LDG.64) ----
    float w00[VPT], w10[VPT], w01[VPT], w11[VPT], dzv[VPT], ezv[VPT];
    uint2 A0[VPT], A1[VPT], B0[VPT], B1[VPT];
    bool  xeq[VPT];

#pragma unroll
    for (int v = 0; v < VPT; ++v) {
        const int y = yb + v;
        const float xf = fxv[v] + (float)x;
        const float yf = fyv[v] + (float)y;
        const float zf = fzv[v] + (float)z;

        int x0 = (int)floorf(xf);
        int y0 = (int)floorf(yf);
        int z0 = (int)floorf(zf);
        // upper corner from UNclamped lower+1, then clamp (matches ref)
        const int x1 = min(max(x0 + 1, 0), Wd - 1);
        const int y1 = min(max(y0 + 1, 0), Hd - 1);
        const int z1 = min(max(z0 + 1, 0), Dd - 1);
        x0 = min(max(x0, 0), Wd - 1);
        y0 = min(max(y0, 0), Hd - 1);
        z0 = min(max(z0, 0), Dd - 1);

        const float dx = (float)x1 - xf;
        const float dy = (float)y1 - yf;
        const float dz = (float)z1 - zf;
        const float ex = 1.0f - dx;
        const float ey = 1.0f - dy;

        w00[v] = dx * dy;
        w10[v] = dx * ey;
        w01[v] = ex * dy;
        w11[v] = ex * ey;
        dzv[v] = dz;
        ezv[v] = 1.0f - dz;
        xeq[v] = (x1 == x0);

        const int r00 = z0 * HWd + y0 * Wd + x0;
        const int r10 = z0 * HWd + y1 * Wd + x0;
        const int r01 = z1 * HWd + y0 * Wd + x0;
        const int r11 = z1 * HWd + y1 * Wd + x0;

        A0[v] = __ldg(Ic + r00);
        A1[v] = __ldg(Ic + r10);
        B0[v] = __ldg(Ic + r01);
        B1[v] = __ldg(Ic + r11);
    }

    // ---- Stage C: clamp-fix, convert, reduce, store ----
#pragma unroll
    for (int v = 0; v < VPT; ++v) {
        if (xeq[v]) {   // below-range x clamp: hi pair := lo pair
            A0[v].y = A0[v].x;
            A1[v].y = A1[v].x;
            B0[v].y = B0[v].x;
            B1[v].y = B1[v].x;
        }

        const float2 a0l = __half22float2(u_to_h2(A0[v].x));
        const float2 a0h = __half22float2(u_to_h2(A0[v].y));
        const float2 a1l = __half22float2(u_to_h2(A1[v].x));
        const float2 a1h = __half22float2(u_to_h2(A1[v].y));
        const float2 b0l = __half22float2(u_to_h2(B0[v].x));
        const float2 b0h = __half22float2(u_to_h2(B0[v].y));
        const float2 b1l = __half22float2(u_to_h2(B1[v].x));
        const float2 b1h = __half22float2(u_to_h2(B1[v].y));

        const float p0c0 = w00[v]*a0l.x + w10[v]*a1l.x + w01[v]*a0h.x + w11[v]*a1h.x;
        const float p0c1 = w00[v]*a0l.y + w10[v]*a1l.y + w01[v]*a0h.y + w11[v]*a1h.y;
        const float p1c0 = w00[v]*b0l.x + w10[v]*b1l.x + w01[v]*b0h.x + w11[v]*b1h.x;
        const float p1c1 = w00[v]*b0l.y + w10[v]*b1l.y + w01[v]*b0h.y + w11[v]*b1h.y;

        const int s = s0 + v * Wd;
        ob[s]        = dzv[v] * p0c0 + ezv[v] * p1c0;
        ob[s + DHWd] = dzv[v] * p0c1 + ezv[v] * p1c1;
    }
}

extern "C" void kernel_launch(void* const* d_in, const int* in_sizes, int n_in,
                              void* d_out, int out_size)
{
    const float* I    = (const float*)d_in[0];
    const float* flow = (const float*)d_in[1];
    float* out        = (float*)d_out;

    dim3 pblock(112, 2, 1);                 // 224 thr
    dim3 pgrid(Hd / 2, Dd, Bd);
    pack_kernel<<<pgrid, pblock>>>(I);

    dim3 block(Wd, 1, 1);                   // 224 thr
    dim3 grid(Hd / VPT, Dd, Bd);            // 48 x 160 x 2
    warp3d_kernel<<<grid, block>>>(flow, out);
}

// round 11
// speedup vs baseline: 1.3000x; 1.0348x over previous
#include <cuda_runtime.h>
#include <cuda_fp16.h>

// warp3D: out[b,c,z,y,x] = trilinear gather of I at (x+fx, y+fy, z+fz)
// B=2, C=2, D=160, H=192, W=224, fp32 in/out.
//
// Pass 1: pack I -> fp16 "half4" per voxel (8 B):
//   It[b,z,y,x] = h(c0[x]), h(c1[x]), h(c0[x+1]), h(c1[x+1])
// Pass 2: 4 x 8B gathers per voxel; FOUR voxels per thread (y-quad), all
//   loads issued before any reduction. __launch_bounds__(224,1) so ptxas
//   keeps the full load pipeline in registers instead of re-serializing
//   it to hit a 32-reg occupancy target (R10 post-mortem).

#define Wd 224
#define Hd 192
#define Dd 160
#define Bd 2
#define HWd (Hd * Wd)            // 43008
#define DHWd (Dd * HWd)          // 6881280
#define VPT 4                    // voxels per thread (along y)

__device__ __forceinline__ unsigned int h2_to_u(__half2 h) {
    return *reinterpret_cast<unsigned int*>(&h);
}
__device__ __forceinline__ __half2 u_to_h2(unsigned int u) {
    return *reinterpret_cast<__half2*>(&u);
}

// 13.76M voxels * 8B = 110 MB scratch
__device__ uint2 g_It[(long)Bd * DHWd];

// Pack: 2 voxels/thread, float2 loads, one STG.128 per pair (coalesced).
__global__ __launch_bounds__(224) void pack_kernel(const float* __restrict__ I)
{
    const int m = threadIdx.x;                 // 0..111 (x pair = 2m, 2m+1)
    const int y = blockIdx.x * 2 + threadIdx.y;
    const int z = blockIdx.y;
    const int b = blockIdx.z;

    const int x = 2 * m;
    const int s = z * HWd + y * Wd + x;
    const float* __restrict__ I0 = I + (long)b * 2 * DHWd;
    const float* __restrict__ I1 = I0 + DHWd;

    const float2 a = __ldg((const float2*)(I0 + s));   // c0[x], c0[x+1]
    const float2 c = __ldg((const float2*)(I1 + s));   // c1[x], c1[x+1]
    const int sn = s - x + min(x + 2, Wd - 1);          // x+2, edge-clamped
    const float n0 = __ldg(I0 + sn);
    const float n1 = __ldg(I1 + sn);

    const unsigned int lo0 = h2_to_u(__floats2half2_rn(a.x, c.x));
    const unsigned int mid = h2_to_u(__floats2half2_rn(a.y, c.y));
    const unsigned int hi1 = h2_to_u(__floats2half2_rn(n0, n1));

    uint4 v;
    v.x = lo0; v.y = mid;      // voxel x
    v.z = mid; v.w = hi1;      // voxel x+1
    *reinterpret_cast<uint4*>(g_It + (long)b * DHWd + s) = v;
}

// Gather: block 224 thr = one x-row; each thread does VPT voxels (y..y+3).
// minBlocksPerMultiprocessor=1 -> generous register budget for the pipeline.
__global__ __launch_bounds__(Wd, 1) void warp3d_kernel(
    const float* __restrict__ flow,
    float* __restrict__ out)
{
    const int x  = threadIdx.x;          // 0..223
    const int yb = blockIdx.x * VPT;     // 0..188 step 4
    const int z  = blockIdx.y;           // 0..159
    const int b  = blockIdx.z;           // 0..1

    const float* __restrict__ fb = flow + (long)b * 3 * DHWd;
    const uint2* __restrict__ Ic = g_It + (long)b * DHWd;
    float* __restrict__ ob = out + (long)b * 2 * DHWd;

    const int s0 = z * HWd + yb * Wd + x;

    // ---- Stage A: all flow loads in flight (12 LDG.32) ----
    float fxv[VPT], fyv[VPT], fzv[VPT];
#pragma unroll
    for (int v = 0; v < VPT; ++v) {
        const int s = s0 + v * Wd;
        fxv[v] = __ldg(fb + s);
        fyv[v] = __ldg(fb + s + DHWd);
        fzv[v] = __ldg(fb + s + 2L * DHWd);
    }

    // ---- Stage B: coords + all gathers in flight (16 LDG.64) ----
    float w00[VPT], w10[VPT], w01[VPT], w11[VPT], dzv[VPT], ezv[VPT];
    uint2 A0[VPT], A1[VPT], B0[VPT], B1[VPT];
    bool  xeq[VPT];

#pragma unroll
    for (int v = 0; v < VPT; ++v) {
        const int y = yb + v;
        const float xf = fxv[v] + (float)x;
        const float yf = fyv[v] + (float)y;
        const float zf = fzv[v] + (float)z;

        int x0 = (int)floorf(xf);
        int y0 = (int)floorf(yf);
        int z0 = (int)floorf(zf);
        // upper corner from UNclamped lower+1, then clamp (matches ref)
        const int x1 = min(max(x0 + 1, 0), Wd - 1);
        const int y1 = min(max(y0 + 1, 0), Hd - 1);
        const int z1 = min(max(z0 + 1, 0), Dd - 1);
        x0 = min(max(x0, 0), Wd - 1);
        y0 = min(max(y0, 0), Hd - 1);
        z0 = min(max(z0, 0), Dd - 1);

        const float dx = (float)x1 - xf;
        const float dy = (float)y1 - yf;
        const float dz = (float)z1 - zf;
        const float ex = 1.0f - dx;
        const float ey = 1.0f - dy;

        w00[v] = dx * dy;
        w10[v] = dx * ey;
        w01[v] = ex * dy;
        w11[v] = ex * ey;
        dzv[v] = dz;
        ezv[v] = 1.0f - dz;
        xeq[v] = (x1 == x0);

        const int r00 = z0 * HWd + y0 * Wd + x0;
        const int r10 = z0 * HWd + y1 * Wd + x0;
        const int r01 = z1 * HWd + y0 * Wd + x0;
        const int r11 = z1 * HWd + y1 * Wd + x0;

        A0[v] = __ldg(Ic + r00);
        A1[v] = __ldg(Ic + r10);
        B0[v] = __ldg(Ic + r01);
        B1[v] = __ldg(Ic + r11);
    }

    // ---- Stage C: clamp-fix, convert, reduce, store ----
#pragma unroll
    for (int v = 0; v < VPT; ++v) {
        if (xeq[v]) {   // below-range x clamp: hi pair := lo pair
            A0[v].y = A0[v].x;
            A1[v].y = A1[v].x;
            B0[v].y = B0[v].x;
            B1[v].y = B1[v].x;
        }

        const float2 a0l = __half22float2(u_to_h2(A0[v].x));
        const float2 a0h = __half22float2(u_to_h2(A0[v].y));
        const float2 a1l = __half22float2(u_to_h2(A1[v].x));
        const float2 a1h = __half22float2(u_to_h2(A1[v].y));
        const float2 b0l = __half22float2(u_to_h2(B0[v].x));
        const float2 b0h = __half22float2(u_to_h2(B0[v].y));
        const float2 b1l = __half22float2(u_to_h2(B1[v].x));
        const float2 b1h = __half22float2(u_to_h2(B1[v].y));

        const float p0c0 = w00[v]*a0l.x + w10[v]*a1l.x + w01[v]*a0h.x + w11[v]*a1h.x;
        const float p0c1 = w00[v]*a0l.y + w10[v]*a1l.y + w01[v]*a0h.y + w11[v]*a1h.y;
        const float p1c0 = w00[v]*b0l.x + w10[v]*b1l.x + w01[v]*b0h.x + w11[v]*b1h.x;
        const float p1c1 = w00[v]*b0l.y + w10[v]*b1l.y + w01[v]*b0h.y + w11[v]*b1h.y;

        const int s = s0 + v * Wd;
        ob[s]        = dzv[v] * p0c0 + ezv[v] * p1c0;
        ob[s + DHWd] = dzv[v] * p0c1 + ezv[v] * p1c1;
    }
}

extern "C" void kernel_launch(void* const* d_in, const int* in_sizes, int n_in,
                              void* d_out, int out_size)
{
    const float* I    = (const float*)d_in[0];
    const float* flow = (const float*)d_in[1];
    float* out        = (float*)d_out;

    dim3 pblock(112, 2, 1);                 // 224 thr
    dim3 pgrid(Hd / 2, Dd, Bd);
    pack_kernel<<<pgrid, pblock>>>(I);

    dim3 block(Wd, 1, 1);                   // 224 thr
    dim3 grid(Hd / VPT, Dd, Bd);            // 48 x 160 x 2
    warp3d_kernel<<<grid, block>>>(flow, out);
}

// round 12
// speedup vs baseline: 1.3827x; 1.0637x over previous
#include <cuda_runtime.h>
#include <cuda_fp16.h>

// warp3D: out[b,c,z,y,x] = trilinear gather of I at (x+fx, y+fy, z+fz)
// B=2, C=2, D=160, H=192, W=224, fp32 in/out.
//
// Pass 1: pack I -> fp16 "half4" per voxel (8 B):
//   It[b,z,y,x] = h(c0[x]), h(c1[x]), h(c0[x+1]), h(c1[x+1])
//   x-quad per thread: 2xLDG.128 + 2xLDG.32 -> 2xSTG.128.
// Pass 2: 4 x 8B gathers per voxel; 4 voxels per thread (y-quad), all loads
//   issued before reduction. __launch_bounds__(224,5): ~58 regs -> 5 blocks
//   /SM = 35 warps, balancing per-warp MLP against warp count (R10/R11
//   bracketed the tradeoff).

#define Wd 224
#define Hd 192
#define Dd 160
#define Bd 2
#define HWd (Hd * Wd)            // 43008
#define DHWd (Dd * HWd)          // 6881280
#define VPT 4                    // voxels per thread (along y)

__device__ __forceinline__ unsigned int h2_to_u(__half2 h) {
    return *reinterpret_cast<unsigned int*>(&h);
}
__device__ __forceinline__ __half2 u_to_h2(unsigned int u) {
    return *reinterpret_cast<__half2*>(&u);
}

// 13.76M voxels * 8B = 110 MB scratch
__device__ uint2 g_It[(long)Bd * DHWd];

// Pack: thread = x-quad (4 voxels). Block (56,4) = 224 thr covers 4 y-rows.
__global__ __launch_bounds__(224) void pack_kernel(const float* __restrict__ I)
{
    const int q = threadIdx.x;                 // 0..55  (x quad = 4q..4q+3)
    const int y = blockIdx.x * 4 + threadIdx.y;
    const int z = blockIdx.y;
    const int b = blockIdx.z;

    const int x = 4 * q;
    const int s = z * HWd + y * Wd + x;        // 16B aligned (x mult of 4)
    const float* __restrict__ I0 = I + (long)b * 2 * DHWd;
    const float* __restrict__ I1 = I0 + DHWd;

    const float4 a = __ldg((const float4*)(I0 + s));   // c0[x..x+3]
    const float4 c = __ldg((const float4*)(I1 + s));   // c1[x..x+3]
    const int sn = s - x + min(x + 4, Wd - 1);          // x+4, edge-clamped
    const float n0 = __ldg(I0 + sn);
    const float n1 = __ldg(I1 + sn);

    const unsigned int e0 = h2_to_u(__floats2half2_rn(a.x, c.x));  // x
    const unsigned int e1 = h2_to_u(__floats2half2_rn(a.y, c.y));  // x+1
    const unsigned int e2 = h2_to_u(__floats2half2_rn(a.z, c.z));  // x+2
    const unsigned int e3 = h2_to_u(__floats2half2_rn(a.w, c.w));  // x+3
    const unsigned int e4 = h2_to_u(__floats2half2_rn(n0,  n1));   // x+4

    uint4* __restrict__ dst = reinterpret_cast<uint4*>(g_It + (long)b * DHWd + s);
    dst[0] = make_uint4(e0, e1, e1, e2);   // voxels x, x+1
    dst[1] = make_uint4(e2, e3, e3, e4);   // voxels x+2, x+3
}

// Gather: block 224 thr = one x-row; each thread does VPT voxels (y..y+3).
// minBlocks=5 -> regs capped ~58 -> 5 blocks/SM (35 warps).
__global__ __launch_bounds__(Wd, 5) void warp3d_kernel(
    const float* __restrict__ flow,
    float* __restrict__ out)
{
    const int x  = threadIdx.x;          // 0..223
    const int yb = blockIdx.x * VPT;     // 0..188 step 4
    const int z  = blockIdx.y;           // 0..159
    const int b  = blockIdx.z;           // 0..1

    const float* __restrict__ fb = flow + (long)b * 3 * DHWd;
    const uint2* __restrict__ Ic = g_It + (long)b * DHWd;
    float* __restrict__ ob = out + (long)b * 2 * DHWd;

    const int s0 = z * HWd + yb * Wd + x;

    // ---- Stage A: all flow loads in flight (12 LDG.32) ----
    float fxv[VPT], fyv[VPT], fzv[VPT];
#pragma unroll
    for (int v = 0; v < VPT; ++v) {
        const int s = s0 + v * Wd;
        fxv[v] = __ldg(fb + s);
        fyv[v] = __ldg(fb + s + DHWd);
        fzv[v] = __ldg(fb + s + 2L * DHWd);
    }

    // ---- Stage B: coords + all gathers in flight (16 LDG.64) ----
    float w00[VPT], w10[VPT], w01[VPT], w11[VPT], dzv[VPT], ezv[VPT];
    uint2 A0[VPT], A1[VPT], B0[VPT], B1[VPT];
    bool  xeq[VPT];

#pragma unroll
    for (int v = 0; v < VPT; ++v) {
        const int y = yb + v;
        const float xf = fxv[v] + (float)x;
        const float yf = fyv[v] + (float)y;
        const float zf = fzv[v] + (float)z;

        int x0 = (int)floorf(xf);
        int y0 = (int)floorf(yf);
        int z0 = (int)floorf(zf);
        // upper corner from UNclamped lower+1, then clamp (matches ref)
        const int x1 = min(max(x0 + 1, 0), Wd - 1);
        const int y1 = min(max(y0 + 1, 0), Hd - 1);
        const int z1 = min(max(z0 + 1, 0), Dd - 1);
        x0 = min(max(x0, 0), Wd - 1);
        y0 = min(max(y0, 0), Hd - 1);
        z0 = min(max(z0, 0), Dd - 1);

        const float dx = (float)x1 - xf;
        const float dy = (float)y1 - yf;
        const float dz = (float)z1 - zf;
        const float ex = 1.0f - dx;
        const float ey = 1.0f - dy;

        w00[v] = dx * dy;
        w10[v] = dx * ey;
        w01[v] = ex * dy;
        w11[v] = ex * ey;
        dzv[v] = dz;
        ezv[v] = 1.0f - dz;
        xeq[v] = (x1 == x0);

        const int r00 = z0 * HWd + y0 * Wd + x0;
        const int r10 = z0 * HWd + y1 * Wd + x0;
        const int r01 = z1 * HWd + y0 * Wd + x0;
        const int r11 = z1 * HWd + y1 * Wd + x0;

        A0[v] = __ldg(Ic + r00);
        A1[v] = __ldg(Ic + r10);
        B0[v] = __ldg(Ic + r01);
        B1[v] = __ldg(Ic + r11);
    }

    // ---- Stage C: clamp-fix, convert, reduce, store ----
#pragma unroll
    for (int v = 0; v < VPT; ++v) {
        if (xeq[v]) {   // below-range x clamp: hi pair := lo pair
            A0[v].y = A0[v].x;
            A1[v].y = A1[v].x;
            B0[v].y = B0[v].x;
            B1[v].y = B1[v].x;
        }

        const float2 a0l = __half22float2(u_to_h2(A0[v].x));
        const float2 a0h = __half22float2(u_to_h2(A0[v].y));
        const float2 a1l = __half22float2(u_to_h2(A1[v].x));
        const float2 a1h = __half22float2(u_to_h2(A1[v].y));
        const float2 b0l = __half22float2(u_to_h2(B0[v].x));
        const float2 b0h = __half22float2(u_to_h2(B0[v].y));
        const float2 b1l = __half22float2(u_to_h2(B1[v].x));
        const float2 b1h = __half22float2(u_to_h2(B1[v].y));

        const float p0c0 = w00[v]*a0l.x + w10[v]*a1l.x + w01[v]*a0h.x + w11[v]*a1h.x;
        const float p0c1 = w00[v]*a0l.y + w10[v]*a1l.y + w01[v]*a0h.y + w11[v]*a1h.y;
        const float p1c0 = w00[v]*b0l.x + w10[v]*b1l.x + w01[v]*b0h.x + w11[v]*b1h.x;
        const float p1c1 = w00[v]*b0l.y + w10[v]*b1l.y + w01[v]*b0h.y + w11[v]*b1h.y;

        const int s = s0 + v * Wd;
        ob[s]        = dzv[v] * p0c0 + ezv[v] * p1c0;
        ob[s + DHWd] = dzv[v] * p0c1 + ezv[v] * p1c1;
    }
}

extern "C" void kernel_launch(void* const* d_in, const int* in_sizes, int n_in,
                              void* d_out, int out_size)
{
    const float* I    = (const float*)d_in[0];
    const float* flow = (const float*)d_in[1];
    float* out        = (float*)d_out;

    dim3 pblock(56, 4, 1);                  // 224 thr
    dim3 pgrid(Hd / 4, Dd, Bd);             // 48 x 160 x 2
    pack_kernel<<<pgrid, pblock>>>(I);

    dim3 block(Wd, 1, 1);                   // 224 thr
    dim3 grid(Hd / VPT, Dd, Bd);            // 48 x 160 x 2
    warp3d_kernel<<<grid, block>>>(flow, out);
}